// round 14
// baseline (speedup 1.0000x reference)
#include <cuda_runtime.h>
#include <cuda_fp16.h>
#include <math.h>
#include <stdint.h>

// Problem constants
#define B_    2
#define LQ_   21760
#define C_    256
#define NHEAD 8
#define KPT   4
#define NL_   6
#define FF_   1024
#define DK_   32
#define MROWS (B_ * LQ_)          // 43520
#define NPACK 640                 // 256 (v) + 256 (off) + 128 (att)
#define NOW   384                 // off|att compact row width

// ---------------------------------------------------------------------------
// Device scratch (no runtime allocation)
// ---------------------------------------------------------------------------
__device__ float g_x    [MROWS * C_];
__device__ float g_xp   [MROWS * C_];
__device__ float g_ow   [MROWS * NOW];    // off (256) | att (128), fp32

__device__ __half g_v_h [MROWS * C_];     // sampled-value tensor, fp16
__device__ __half g_a_h [MROWS * C_];     // xp / attn / ln1-out fp16 (reused)
__device__ __half g_h_h [MROWS * FF_];    // hid fp16

// fp16 weights, [N,K] transposed layout (single-rounded)
__device__ __half g_wproj[NL_ * NPACK * C_];
__device__ __half g_wo   [NL_ * C_ * C_];
__device__ __half g_w1   [NL_ * FF_ * C_];
__device__ __half g_w2   [NL_ * C_ * FF_];
__device__ float  g_bpack[NL_ * NPACK];

// ---------------------------------------------------------------------------
// Helpers
// ---------------------------------------------------------------------------
__device__ __forceinline__ uint32_t smem_u32(const void* p) {
    uint32_t a;
    asm("{ .reg .u64 t; cvta.to.shared.u64 t, %1; cvt.u32.u64 %0, t; }"
        : "=r"(a) : "l"(p));
    return a;
}

#define MMA_F16(d, a, b0v, b1v)                                               \
    asm volatile("mma.sync.aligned.m16n8k16.row.col.f32.f16.f16.f32 "         \
        "{%0,%1,%2,%3}, {%4,%5,%6,%7}, {%8,%9}, {%0,%1,%2,%3};"               \
        : "+f"((d)[0]), "+f"((d)[1]), "+f"((d)[2]), "+f"((d)[3])              \
        : "r"((a)[0]), "r"((a)[1]), "r"((a)[2]), "r"((a)[3]),                 \
          "r"(b0v), "r"(b1v))

#define LDMATRIX_X4(r0, r1, r2, r3, addr)                                     \
    asm volatile("ldmatrix.sync.aligned.m8n8.x4.shared.b16 {%0,%1,%2,%3}, [%4];" \
        : "=r"(r0), "=r"(r1), "=r"(r2), "=r"(r3) : "r"(addr))

#define CP_ASYNC16(saddr, gptr)                                               \
    asm volatile("cp.async.cg.shared.global [%0], [%1], 16;"                  \
        :: "r"(saddr), "l"(gptr))

// ---------------------------------------------------------------------------
// Weight packing (fp32 [K,N] -> fp16 [N,K])
// ---------------------------------------------------------------------------
__global__ void pack_proj_w(const float* __restrict__ Wv,
                            const float* __restrict__ Woff,
                            const float* __restrict__ Wat,
                            __half* __restrict__ Bh) {
    int idx = blockIdx.x * blockDim.x + threadIdx.x;   // NL*640*256
    if (idx >= NL_ * NPACK * C_) return;
    int k = idx & 255;
    int n = (idx >> 8) % NPACK;
    int l = idx / (NPACK * C_);
    float v;
    if (n < 256)      v = Wv  [((size_t)l * C_ + k) * 256 + n];
    else if (n < 512) v = Woff[((size_t)l * C_ + k) * 256 + (n - 256)];
    else              v = Wat [((size_t)l * C_ + k) * 128 + (n - 512)];
    Bh[idx] = __float2half_rn(v);
}

__global__ void pack_w(const float* __restrict__ W,
                       __half* __restrict__ Bh, int K, int N) {
    int idx = blockIdx.x * blockDim.x + threadIdx.x;   // NL*N*K
    if (idx >= NL_ * N * K) return;
    int k = idx % K;
    int n = (idx / K) % N;
    int l = idx / (N * K);
    Bh[idx] = __float2half_rn(W[(size_t)l * K * N + (size_t)k * N + n]);
}

__global__ void packb_kernel(const float* __restrict__ bv,
                             const float* __restrict__ boff,
                             const float* __restrict__ bat,
                             float* __restrict__ bp) {
    int idx = blockIdx.x * blockDim.x + threadIdx.x;
    if (idx >= NL_ * NPACK) return;
    int n = idx % NPACK;
    int l = idx / NPACK;
    float val;
    if (n < 256)      val = bv  [(size_t)l * 256 + n];
    else if (n < 512) val = boff[(size_t)l * 256 + (n - 256)];
    else              val = bat [(size_t)l * 128 + (n - 512)];
    bp[idx] = val;
}

// ---------------------------------------------------------------------------
// addpos (layer 0 only): xp = x + pos -> fp32 + fp16
// ---------------------------------------------------------------------------
__global__ void addpos_kernel(const float* __restrict__ x,
                              const float* __restrict__ pos,
                              float* __restrict__ xp,
                              __half* __restrict__ ph, int n4) {
    int i = blockIdx.x * blockDim.x + threadIdx.x;
    if (i >= n4) return;
    float4 a = ((const float4*)x)[i];
    float4 b = ((const float4*)pos)[i];
    float4 o;
    o.x = a.x + b.x; o.y = a.y + b.y; o.z = a.z + b.z; o.w = a.w + b.w;
    ((float4*)xp)[i] = o;
    ((__half2*)ph)[i * 2]     = __halves2half2(__float2half_rn(o.x), __float2half_rn(o.y));
    ((__half2*)ph)[i * 2 + 1] = __halves2half2(__float2half_rn(o.z), __float2half_rn(o.w));
}

// ---------------------------------------------------------------------------
// mma.sync fp16 GEMM: C[M,N] = A[M,K] @ B[N,K]^T + bias.
// Template BMt in {128, 64}; BN=128; 8 warps; 3-stage cp.async pipeline.
// OMODE: 1 = fp16 out, 2 = proj split (v fp16 | ow fp32)
// ---------------------------------------------------------------------------
template<int BMt, int RELU, int OMODE>
__global__ __launch_bounds__(256, 2)
void mma_gemm(const __half* __restrict__ A,
              const __half* __restrict__ Bm,
              const float* __restrict__ bias,
              __half* __restrict__ Chf,
              float* __restrict__ Cow,
              int N, int K) {
    constexpr int MW    = BMt / 32;
    constexpr int NW    = 8 / MW;
    constexpr int WN    = 128 / NW;
    constexpr int NG    = WN / 16;
    constexpr int ROWS  = BMt + 128;
    constexpr int STAGE = ROWS * 128;
    constexpr int PERT  = ROWS * 8 / 256;

    extern __shared__ uint8_t smem[];
    const int tid  = threadIdx.x;
    const int wid  = tid >> 5;
    const int lane = tid & 31;
    const int brow = blockIdx.y * BMt;
    const int bcol = blockIdx.x * 128;
    const int kIters = K >> 6;

    const uint32_t smbase = smem_u32(smem);

    auto load_tile = [&](int k, int buf) {
        uint32_t sbuf = smbase + buf * STAGE;
        const int koff = k << 6;
        #pragma unroll
        for (int i = 0; i < PERT; i++) {
            int cid = tid + (i << 8);
            int row = cid >> 3;
            int col = cid & 7;
            const __half* g;
            if (row < BMt) g = A  + (size_t)(brow + row) * K + koff + col * 8;
            else           g = Bm + (size_t)(bcol + row - BMt) * K + koff + col * 8;
            uint32_t sw = row * 128 + (((uint32_t)(col ^ (row & 7))) << 4);
            CP_ASYNC16(sbuf + sw, g);
        }
    };

    const int wm = (wid % MW) * 32;
    const int wn = (wid / MW) * WN;

    float acc[2][2 * NG][4];
    #pragma unroll
    for (int mi = 0; mi < 2; mi++)
        #pragma unroll
        for (int nj = 0; nj < 2 * NG; nj++)
            #pragma unroll
            for (int r = 0; r < 4; r++) acc[mi][nj][r] = 0.0f;

    auto compute = [&](int buf) {
        uint32_t sA = smbase + buf * STAGE;
        uint32_t sB = sA + BMt * 128;
        #pragma unroll
        for (int ks = 0; ks < 4; ks++) {
            uint32_t a[2][4];
            const int c = ks * 2 + (lane >> 4);
            #pragma unroll
            for (int mi = 0; mi < 2; mi++) {
                int r = wm + mi * 16 + (lane & 15);
                uint32_t addr = sA + r * 128 + ((c ^ (r & 7)) << 4);
                LDMATRIX_X4(a[mi][0], a[mi][1], a[mi][2], a[mi][3], addr);
            }
            #pragma unroll
            for (int ng = 0; ng < NG; ng++) {
                int r = wn + ng * 16 + (lane & 15);
                uint32_t soff = r * 128 + ((c ^ (r & 7)) << 4);
                uint32_t b0, b1, b2, b3;
                LDMATRIX_X4(b0, b1, b2, b3, sB + soff);
                #pragma unroll
                for (int mi = 0; mi < 2; mi++) {
                    MMA_F16(acc[mi][ng * 2 + 0], a[mi], b0, b2);
                    MMA_F16(acc[mi][ng * 2 + 1], a[mi], b1, b3);
                }
            }
        }
    };

    load_tile(0, 0);
    asm volatile("cp.async.commit_group;" ::: "memory");
    if (kIters > 1) {
        load_tile(1, 1);
        asm volatile("cp.async.commit_group;" ::: "memory");
    }
    for (int t = 0; t < kIters; t++) {
        if (t + 1 < kIters)
            asm volatile("cp.async.wait_group 1;" ::: "memory");
        else
            asm volatile("cp.async.wait_group 0;" ::: "memory");
        __syncthreads();
        if (t + 2 < kIters) {
            load_tile(t + 2, (t + 2) % 3);
            asm volatile("cp.async.commit_group;" ::: "memory");
        }
        compute(t % 3);
    }

    const int tr = lane >> 2;
    const int tc = (lane & 3) * 2;
    #pragma unroll
    for (int mi = 0; mi < 2; mi++) {
        #pragma unroll
        for (int nj = 0; nj < 2 * NG; nj++) {
            const int col = bcol + wn + nj * 8 + tc;
            const float bb0 = bias[col], bb1 = bias[col + 1];
            #pragma unroll
            for (int rr = 0; rr < 2; rr++) {
                const int row = brow + wm + mi * 16 + rr * 8 + tr;
                float v0 = acc[mi][nj][rr * 2 + 0] + bb0;
                float v1 = acc[mi][nj][rr * 2 + 1] + bb1;
                if (RELU) { v0 = fmaxf(v0, 0.f); v1 = fmaxf(v1, 0.f); }
                if (OMODE == 1) {
                    *(__half2*)(Chf + (size_t)row * N + col) =
                        __halves2half2(__float2half_rn(v0), __float2half_rn(v1));
                } else {
                    if (col < 256) {
                        *(__half2*)(Chf + (size_t)row * C_ + col) =
                            __halves2half2(__float2half_rn(v0), __float2half_rn(v1));
                    } else {
                        float2 o; o.x = v0; o.y = v1;
                        *(float2*)(Cow + (size_t)row * NOW + (col - 256)) = o;
                    }
                }
            }
        }
    }
}

// ---------------------------------------------------------------------------
// Fused GEMM + residual + LayerNorm.
// out = LN(resid + A@B^T + bias) * s + bb  [+ pos if POSADD]
// BM=32, BN=256 (full row). 8 warps ALL in N: warp tile 32Mx32N -> 2:1
// MMA:ldmatrix ratio (same as plain BM=64 kernel). 3-stage pipeline,
// one sync per k-iter. Grid = M/32 = 1360 blocks (4.59 waves).
// FINAL: write fp32 only (network output); else fp32 + fp16.
// ---------------------------------------------------------------------------
template<int POSADD, int FINAL>
__global__ __launch_bounds__(256, 2)
void mma_gemm_ln(const __half* __restrict__ A,
                 const __half* __restrict__ Bm,
                 const float* __restrict__ bias,
                 const float* __restrict__ resid,
                 const float* __restrict__ s,
                 const float* __restrict__ bb,
                 const float* __restrict__ pos,
                 float* __restrict__ outF,
                 __half* __restrict__ outH,
                 int K) {
    constexpr int STAGE = 288 * 128;   // (32 A-rows + 256 B-rows) * 128B
    extern __shared__ uint8_t smem[];
    const int tid  = threadIdx.x;
    const int wid  = tid >> 5;
    const int lane = tid & 31;
    const int brow = blockIdx.x * 32;
    const int kIters = K >> 6;
    const uint32_t smbase = smem_u32(smem);

    auto load_tile = [&](int k, int buf) {
        uint32_t sbuf = smbase + buf * STAGE;
        const int koff = k << 6;
        #pragma unroll
        for (int i = 0; i < 9; i++) {          // 288*8/256 = 9 chunks/thread
            int cid = tid + (i << 8);
            int row = cid >> 3;
            int col = cid & 7;
            const __half* g = (row < 32)
                ? A  + (size_t)(brow + row) * K + koff + col * 8
                : Bm + (size_t)(row - 32) * K + koff + col * 8;
            uint32_t sw = row * 128 + (((uint32_t)(col ^ (row & 7))) << 4);
            CP_ASYNC16(sbuf + sw, g);
        }
    };

    const int wn = wid * 32;             // each warp: all 32 M-rows, 32 N-cols

    float acc[2][4][4];                  // [mi][nj][r], 32 regs
    #pragma unroll
    for (int mi = 0; mi < 2; mi++)
        #pragma unroll
        for (int nj = 0; nj < 4; nj++)
            #pragma unroll
            for (int r = 0; r < 4; r++) acc[mi][nj][r] = 0.0f;

    auto compute = [&](int buf) {
        uint32_t sA = smbase + buf * STAGE;
        uint32_t sB = sA + 32 * 128;
        #pragma unroll
        for (int ks = 0; ks < 4; ks++) {
            const int c = ks * 2 + (lane >> 4);
            uint32_t a[2][4];
            #pragma unroll
            for (int mi = 0; mi < 2; mi++) {
                int r = mi * 16 + (lane & 15);
                uint32_t addr = sA + r * 128 + ((c ^ (r & 7)) << 4);
                LDMATRIX_X4(a[mi][0], a[mi][1], a[mi][2], a[mi][3], addr);
            }
            #pragma unroll
            for (int ng = 0; ng < 2; ng++) {
                int r2 = wn + ng * 16 + (lane & 15);
                uint32_t soff = r2 * 128 + ((c ^ (r2 & 7)) << 4);
                uint32_t b0, b1, b2, b3;
                LDMATRIX_X4(b0, b1, b2, b3, sB + soff);
                #pragma unroll
                for (int mi = 0; mi < 2; mi++) {
                    MMA_F16(acc[mi][ng * 2 + 0], a[mi], b0, b2);
                    MMA_F16(acc[mi][ng * 2 + 1], a[mi], b1, b3);
                }
            }
        }
    };

    // 3-stage pipeline, one sync per iteration
    load_tile(0, 0);
    asm volatile("cp.async.commit_group;" ::: "memory");
    if (kIters > 1) {
        load_tile(1, 1);
        asm volatile("cp.async.commit_group;" ::: "memory");
    }
    for (int t = 0; t < kIters; t++) {
        if (t + 1 < kIters)
            asm volatile("cp.async.wait_group 1;" ::: "memory");
        else
            asm volatile("cp.async.wait_group 0;" ::: "memory");
        __syncthreads();
        if (t + 2 < kIters) {
            load_tile(t + 2, (t + 2) % 3);
            asm volatile("cp.async.commit_group;" ::: "memory");
        }
        compute(t % 3);
    }
    __syncthreads();   // protect smem reuse below (no trailing sync in loop)

    // ---- Fused epilogue: residual add + two-pass LayerNorm ----
    const int tr = lane >> 2;            // 0..7
    const int tc = (lane & 3) * 2;       // 0,2,4,6
    float* red = (float*)smem;           // 32 rows x 8 warps = 1KB

    float mean_[2][2], inv_[2][2];

    // Pass A: t = acc + bias + resid; row sums
    #pragma unroll
    for (int mi = 0; mi < 2; mi++)
        #pragma unroll
        for (int rr = 0; rr < 2; rr++) {
            int rowl = mi * 16 + rr * 8 + tr;
            size_t rowg = (size_t)(brow + rowl) * C_;
            float sum = 0.f;
            #pragma unroll
            for (int nj = 0; nj < 4; nj++) {
                int col = wn + nj * 8 + tc;
                float2 rv = *(const float2*)(resid + rowg + col);
                float t0 = acc[mi][nj][rr * 2 + 0] + bias[col]     + rv.x;
                float t1 = acc[mi][nj][rr * 2 + 1] + bias[col + 1] + rv.y;
                acc[mi][nj][rr * 2 + 0] = t0;
                acc[mi][nj][rr * 2 + 1] = t1;
                sum += t0 + t1;
            }
            sum += __shfl_xor_sync(0xFFFFFFFF, sum, 1);
            sum += __shfl_xor_sync(0xFFFFFFFF, sum, 2);
            if ((lane & 3) == 0) red[rowl * 8 + wid] = sum;
        }
    __syncthreads();
    #pragma unroll
    for (int mi = 0; mi < 2; mi++)
        #pragma unroll
        for (int rr = 0; rr < 2; rr++) {
            int rowl = mi * 16 + rr * 8 + tr;
            float m = 0.f;
            #pragma unroll
            for (int wj = 0; wj < 8; wj++) m += red[rowl * 8 + wj];
            mean_[mi][rr] = m * (1.0f / C_);
        }
    __syncthreads();

    // Pass B: variance
    #pragma unroll
    for (int mi = 0; mi < 2; mi++)
        #pragma unroll
        for (int rr = 0; rr < 2; rr++) {
            int rowl = mi * 16 + rr * 8 + tr;
            float sq = 0.f;
            #pragma unroll
            for (int nj = 0; nj < 4; nj++) {
                float d0 = acc[mi][nj][rr * 2 + 0] - mean_[mi][rr];
                float d1 = acc[mi][nj][rr * 2 + 1] - mean_[mi][rr];
                sq = fmaf(d0, d0, sq);
                sq = fmaf(d1, d1, sq);
            }
            sq += __shfl_xor_sync(0xFFFFFFFF, sq, 1);
            sq += __shfl_xor_sync(0xFFFFFFFF, sq, 2);
            if ((lane & 3) == 0) red[rowl * 8 + wid] = sq;
        }
    __syncthreads();
    #pragma unroll
    for (int mi = 0; mi < 2; mi++)
        #pragma unroll
        for (int rr = 0; rr < 2; rr++) {
            int rowl = mi * 16 + rr * 8 + tr;
            float sq = 0.f;
            #pragma unroll
            for (int wj = 0; wj < 8; wj++) sq += red[rowl * 8 + wj];
            inv_[mi][rr] = rsqrtf(sq * (1.0f / C_) + 1e-5f);
        }

    // Apply + write
    #pragma unroll
    for (int mi = 0; mi < 2; mi++)
        #pragma unroll
        for (int rr = 0; rr < 2; rr++) {
            int rowl = mi * 16 + rr * 8 + tr;
            size_t rowg = (size_t)(brow + rowl) * C_;
            #pragma unroll
            for (int nj = 0; nj < 4; nj++) {
                int col = wn + nj * 8 + tc;
                float v0 = (acc[mi][nj][rr * 2 + 0] - mean_[mi][rr]) * inv_[mi][rr]
                           * s[col] + bb[col];
                float v1 = (acc[mi][nj][rr * 2 + 1] - mean_[mi][rr]) * inv_[mi][rr]
                           * s[col + 1] + bb[col + 1];
                if (POSADD) {
                    float2 pv = *(const float2*)(pos + rowg + col);
                    v0 += pv.x; v1 += pv.y;
                }
                float2 o; o.x = v0; o.y = v1;
                *(float2*)(outF + rowg + col) = o;
                if (!FINAL)
                    *(__half2*)(outH + rowg + col) =
                        __halves2half2(__float2half_rn(v0), __float2half_rn(v1));
            }
        }
}

// ---------------------------------------------------------------------------
// Deformable attention sampling, half2 channel pairs.
// ---------------------------------------------------------------------------
__constant__ int c_SW[4] = {128, 64, 32, 16};
__constant__ int c_START[4] = {0, 16384, 20480, 21504};

__global__ __launch_bounds__(256)
void deform_kernel(const __half* __restrict__ vh, const float* __restrict__ ow,
                   const float* __restrict__ ref, __half* __restrict__ oh) {
    const int tid  = threadIdx.x;
    const int wblk = tid >> 5;
    const int lane = tid & 31;
    const int sub  = lane >> 4;
    const int li   = lane & 15;
    const int bq   = blockIdx.x * 2 + (wblk >> 2);
    const int h    = ((wblk & 3) << 1) + sub;
    const int b    = bq / LQ_;

    const float* ar = ow + (size_t)bq * NOW + 256 + h * 16;
    float w[16];
    float mx = -1e30f;
    #pragma unroll
    for (int j = 0; j < 16; j++) { w[j] = ar[j]; mx = fmaxf(mx, w[j]); }
    float s = 0.0f;
    #pragma unroll
    for (int j = 0; j < 16; j++) { w[j] = expf(w[j] - mx); s += w[j]; }
    const float inv_s = 1.0f / s;

    const float refx = ref[bq * 2 + 0];
    const float refy = ref[bq * 2 + 1];
    const float* ob = ow + (size_t)bq * NOW + h * 32;
    const __half2* vb2 = (const __half2*)vh
                       + ((size_t)b * LQ_ * C_ + h * DK_) / 2 + li;

    float accx = 0.0f, accy = 0.0f;
    #pragma unroll
    for (int l = 0; l < 4; l++) {
        const int   Wl = c_SW[l];
        const float fw = (float)Wl;
        const int   st = c_START[l];
        #pragma unroll
        for (int k = 0; k < KPT; k++) {
            float ox = ob[l * 8 + k * 2 + 0];
            float oy = ob[l * 8 + k * 2 + 1];
            float x = (refx + ox * (1.0f / fw)) * (fw - 1.0f);
            float y = (refy + oy * (1.0f / fw)) * (fw - 1.0f);
            x = fminf(fmaxf(x, 0.0f), fw - 1.0f);
            y = fminf(fmaxf(y, 0.0f), fw - 1.0f);
            float x0f = floorf(x), y0f = floorf(y);
            int x0 = (int)x0f, y0 = (int)y0f;
            int x1 = min(x0 + 1, Wl - 1);
            int y1 = min(y0 + 1, Wl - 1);
            float wx = x - x0f, wy = y - y0f;
            float aw = w[l * 4 + k] * inv_s;

            float2 v00 = __half22float2(vb2[(size_t)(st + y0 * Wl + x0) * (C_ / 2)]);
            float2 v01 = __half22float2(vb2[(size_t)(st + y0 * Wl + x1) * (C_ / 2)]);
            float2 v10 = __half22float2(vb2[(size_t)(st + y1 * Wl + x0) * (C_ / 2)]);
            float2 v11 = __half22float2(vb2[(size_t)(st + y1 * Wl + x1) * (C_ / 2)]);
            float w00 = (1.0f - wx) * (1.0f - wy);
            float w01 = wx * (1.0f - wy);
            float w10 = (1.0f - wx) * wy;
            float w11 = wx * wy;
            float bx = w00 * v00.x + w01 * v01.x + w10 * v10.x + w11 * v11.x;
            float by = w00 * v00.y + w01 * v01.y + w10 * v10.y + w11 * v11.y;
            accx = fmaf(aw, bx, accx);
            accy = fmaf(aw, by, accy);
        }
    }
    ((__half2*)oh)[((size_t)bq * C_ + h * DK_) / 2 + li] =
        __halves2half2(__float2half_rn(accx), __float2half_rn(accy));
}

// ---------------------------------------------------------------------------
// Host orchestration
// ---------------------------------------------------------------------------
extern "C" void kernel_launch(void* const* d_in, const int* in_sizes, int n_in,
                              void* d_out, int out_size) {
    const float* src  = (const float*)d_in[0];
    const float* pos  = (const float*)d_in[1];
    const float* ref  = (const float*)d_in[2];
    const float* Woff = (const float*)d_in[3];
    const float* boff = (const float*)d_in[4];
    const float* Wat  = (const float*)d_in[5];
    const float* bat  = (const float*)d_in[6];
    const float* Wv   = (const float*)d_in[7];
    const float* bv   = (const float*)d_in[8];
    const float* Wo   = (const float*)d_in[9];
    const float* bo   = (const float*)d_in[10];
    const float* W1   = (const float*)d_in[11];
    const float* b1   = (const float*)d_in[12];
    const float* W2   = (const float*)d_in[13];
    const float* b2   = (const float*)d_in[14];
    const float* n1s  = (const float*)d_in[15];
    const float* n1b  = (const float*)d_in[16];
    const float* n2s  = (const float*)d_in[17];
    const float* n2b  = (const float*)d_in[18];
    float* outp = (float*)d_out;

    float *px, *pxp, *pow, *pbp;
    __half *pvh, *pah, *phh;
    __half *wproj, *wo, *w1, *w2;
    cudaGetSymbolAddress((void**)&px,     g_x);
    cudaGetSymbolAddress((void**)&pxp,    g_xp);
    cudaGetSymbolAddress((void**)&pow,    g_ow);
    cudaGetSymbolAddress((void**)&pbp,    g_bpack);
    cudaGetSymbolAddress((void**)&pvh,    g_v_h);
    cudaGetSymbolAddress((void**)&pah,    g_a_h);
    cudaGetSymbolAddress((void**)&phh,    g_h_h);
    cudaGetSymbolAddress((void**)&wproj,  g_wproj);
    cudaGetSymbolAddress((void**)&wo,     g_wo);
    cudaGetSymbolAddress((void**)&w1,     g_w1);
    cudaGetSymbolAddress((void**)&w2,     g_w2);

    const int M = MROWS;
    const int n4 = M * C_ / 4;
    const int SMEM128 = 3 * 256 * 128;   // 98304 (proj, 3-stage)
    const int SMEM64  = 3 * 192 * 128;   // 73728 (W1, 3-stage)
    const int SMEMLN  = 3 * 288 * 128;   // 110592 (fused LN, 3-stage)

    cudaFuncSetAttribute(mma_gemm<128, 0, 2>,
                         cudaFuncAttributeMaxDynamicSharedMemorySize, SMEM128);
    cudaFuncSetAttribute(mma_gemm<64, 1, 1>,
                         cudaFuncAttributeMaxDynamicSharedMemorySize, SMEM64);
    cudaFuncSetAttribute(mma_gemm_ln<0, 0>,
                         cudaFuncAttributeMaxDynamicSharedMemorySize, SMEMLN);
    cudaFuncSetAttribute(mma_gemm_ln<1, 0>,
                         cudaFuncAttributeMaxDynamicSharedMemorySize, SMEMLN);
    cudaFuncSetAttribute(mma_gemm_ln<0, 1>,
                         cudaFuncAttributeMaxDynamicSharedMemorySize, SMEMLN);

    // Weight packing (deterministic, per call)
    {
        int t0 = NL_ * NPACK * C_;
        pack_proj_w<<<(t0 + 255) / 256, 256>>>(Wv, Woff, Wat, wproj);
        int t1 = NL_ * C_ * C_;
        pack_w<<<(t1 + 255) / 256, 256>>>(Wo, wo, C_, C_);
        int t2 = NL_ * FF_ * C_;
        pack_w<<<(t2 + 255) / 256, 256>>>(W1, w1, C_, FF_);
        pack_w<<<(t2 + 255) / 256, 256>>>(W2, w2, FF_, C_);
        int tb = NL_ * NPACK;
        packb_kernel<<<(tb + 255) / 256, 256>>>(bv, boff, bat, pbp);
    }

    dim3 gAdd((n4 + 255) / 256);
    dim3 gProj(NPACK / 128, M / 128);   // (5, 340)  BM=128
    dim3 gN1024(FF_ / 128, M / 64);     // (8, 680)  BM=64
    dim3 gLNG(M / 32);                  // 1360 blocks, fused GEMM+LN
    dim3 gDef(M / 2);

    // Layer 0 addpos; later layers get it fused into LN2
    addpos_kernel<<<gAdd, 256>>>(src, pos, pxp, pah, n4);

    for (int i = 0; i < NL_; i++) {
        const float* bp_i = pbp + (size_t)i * NPACK;
        const float* bo_i = bo + (size_t)i * C_;
        const float* b1_i = b1 + (size_t)i * FF_;
        const float* b2_i = b2 + (size_t)i * C_;

        // Fused projections -> v fp16 | off/att fp32   (N=640, K=256)
        mma_gemm<128, 0, 2><<<gProj, 256, SMEM128>>>(pah,
            wproj + (size_t)i * NPACK * C_,
            bp_i, pvh, pow, NPACK, C_);

        deform_kernel<<<gDef, 256>>>(pvh, pow, ref, pah);

        // Wo GEMM + LN1 fused: x = LN(xp + attn@Wo + bo); emit px fp32 + pah fp16
        mma_gemm_ln<0, 0><<<gLNG, 256, SMEMLN>>>(pah,
            wo + (size_t)i * C_ * C_, bo_i, pxp,
            n1s + (size_t)i * C_, n1b + (size_t)i * C_, nullptr,
            px, pah, C_);

        // W1 + ReLU -> hid fp16   (N=1024, K=256)
        mma_gemm<64, 1, 1><<<gN1024, 256, SMEM64>>>(pah,
            w1 + (size_t)i * FF_ * C_,
            b1_i, phh, nullptr, FF_, C_);

        // W2 GEMM + LN2 fused
        if (i == NL_ - 1) {
            mma_gemm_ln<0, 1><<<gLNG, 256, SMEMLN>>>(phh,
                w2 + (size_t)i * C_ * FF_, b2_i, px,
                n2s + (size_t)i * C_, n2b + (size_t)i * C_, nullptr,
                outp, nullptr, FF_);
        } else {
            mma_gemm_ln<1, 0><<<gLNG, 256, SMEMLN>>>(phh,
                w2 + (size_t)i * C_ * FF_, b2_i, px,
                n2s + (size_t)i * C_, n2b + (size_t)i * C_, pos,
                pxp, pah, FF_);
        }
    }
}

// round 16
// speedup vs baseline: 1.0298x; 1.0298x over previous
#include <cuda_runtime.h>
#include <cuda_fp16.h>
#include <math.h>
#include <stdint.h>

// Problem constants
#define B_    2
#define LQ_   21760
#define C_    256
#define NHEAD 8
#define KPT   4
#define NL_   6
#define FF_   1024
#define DK_   32
#define MROWS (B_ * LQ_)          // 43520
#define NPACK 640                 // 256 (v) + 256 (off) + 128 (att)
#define NOW   384                 // off|att compact row width

// ---------------------------------------------------------------------------
// Device scratch (no runtime allocation)
// ---------------------------------------------------------------------------
__device__ float g_x    [MROWS * C_];
__device__ float g_xp   [MROWS * C_];
__device__ float g_ow   [MROWS * NOW];    // off (256) | att (128), fp32

__device__ __half g_v_h [MROWS * C_];     // sampled-value tensor, fp16
__device__ __half g_a_h [MROWS * C_];     // xp / attn / ln1-out fp16 (reused)
__device__ __half g_h_h [MROWS * FF_];    // hid fp16

// fp16 weights, [N,K] transposed layout (single-rounded)
__device__ __half g_wproj[NL_ * NPACK * C_];
__device__ __half g_wo   [NL_ * C_ * C_];
__device__ __half g_w1   [NL_ * FF_ * C_];
__device__ __half g_w2   [NL_ * C_ * FF_];
__device__ float  g_bpack[NL_ * NPACK];

// ---------------------------------------------------------------------------
// Helpers
// ---------------------------------------------------------------------------
__device__ __forceinline__ uint32_t smem_u32(const void* p) {
    uint32_t a;
    asm("{ .reg .u64 t; cvta.to.shared.u64 t, %1; cvt.u32.u64 %0, t; }"
        : "=r"(a) : "l"(p));
    return a;
}

#define MMA_F16(d, a, b0v, b1v)                                               \
    asm volatile("mma.sync.aligned.m16n8k16.row.col.f32.f16.f16.f32 "         \
        "{%0,%1,%2,%3}, {%4,%5,%6,%7}, {%8,%9}, {%0,%1,%2,%3};"               \
        : "+f"((d)[0]), "+f"((d)[1]), "+f"((d)[2]), "+f"((d)[3])              \
        : "r"((a)[0]), "r"((a)[1]), "r"((a)[2]), "r"((a)[3]),                 \
          "r"(b0v), "r"(b1v))

#define LDMATRIX_X4(r0, r1, r2, r3, addr)                                     \
    asm volatile("ldmatrix.sync.aligned.m8n8.x4.shared.b16 {%0,%1,%2,%3}, [%4];" \
        : "=r"(r0), "=r"(r1), "=r"(r2), "=r"(r3) : "r"(addr))

#define CP_ASYNC16(saddr, gptr)                                               \
    asm volatile("cp.async.cg.shared.global [%0], [%1], 16;"                  \
        :: "r"(saddr), "l"(gptr))

// ---------------------------------------------------------------------------
// Weight packing (fp32 [K,N] -> fp16 [N,K])
// ---------------------------------------------------------------------------
__global__ void pack_proj_w(const float* __restrict__ Wv,
                            const float* __restrict__ Woff,
                            const float* __restrict__ Wat,
                            __half* __restrict__ Bh) {
    int idx = blockIdx.x * blockDim.x + threadIdx.x;   // NL*640*256
    if (idx >= NL_ * NPACK * C_) return;
    int k = idx & 255;
    int n = (idx >> 8) % NPACK;
    int l = idx / (NPACK * C_);
    float v;
    if (n < 256)      v = Wv  [((size_t)l * C_ + k) * 256 + n];
    else if (n < 512) v = Woff[((size_t)l * C_ + k) * 256 + (n - 256)];
    else              v = Wat [((size_t)l * C_ + k) * 128 + (n - 512)];
    Bh[idx] = __float2half_rn(v);
}

__global__ void pack_w(const float* __restrict__ W,
                       __half* __restrict__ Bh, int K, int N) {
    int idx = blockIdx.x * blockDim.x + threadIdx.x;   // NL*N*K
    if (idx >= NL_ * N * K) return;
    int k = idx % K;
    int n = (idx / K) % N;
    int l = idx / (N * K);
    Bh[idx] = __float2half_rn(W[(size_t)l * K * N + (size_t)k * N + n]);
}

__global__ void packb_kernel(const float* __restrict__ bv,
                             const float* __restrict__ boff,
                             const float* __restrict__ bat,
                             float* __restrict__ bp) {
    int idx = blockIdx.x * blockDim.x + threadIdx.x;
    if (idx >= NL_ * NPACK) return;
    int n = idx % NPACK;
    int l = idx / NPACK;
    float val;
    if (n < 256)      val = bv  [(size_t)l * 256 + n];
    else if (n < 512) val = boff[(size_t)l * 256 + (n - 256)];
    else              val = bat [(size_t)l * 128 + (n - 512)];
    bp[idx] = val;
}

// ---------------------------------------------------------------------------
// addpos (layer 0 only): xp = x + pos -> fp32 + fp16
// ---------------------------------------------------------------------------
__global__ void addpos_kernel(const float* __restrict__ x,
                              const float* __restrict__ pos,
                              float* __restrict__ xp,
                              __half* __restrict__ ph, int n4) {
    int i = blockIdx.x * blockDim.x + threadIdx.x;
    if (i >= n4) return;
    float4 a = ((const float4*)x)[i];
    float4 b = ((const float4*)pos)[i];
    float4 o;
    o.x = a.x + b.x; o.y = a.y + b.y; o.z = a.z + b.z; o.w = a.w + b.w;
    ((float4*)xp)[i] = o;
    ((__half2*)ph)[i * 2]     = __halves2half2(__float2half_rn(o.x), __float2half_rn(o.y));
    ((__half2*)ph)[i * 2 + 1] = __halves2half2(__float2half_rn(o.z), __float2half_rn(o.w));
}

// ---------------------------------------------------------------------------
// mma.sync fp16 GEMM: C[M,N] = A[M,K] @ B[N,K]^T + bias.
// Template BMt in {128, 64}; BN=128; 8 warps; 3-stage cp.async pipeline.
// OMODE: 1 = fp16 out, 2 = proj split (v fp16 | ow fp32)
// ---------------------------------------------------------------------------
template<int BMt, int RELU, int OMODE>
__global__ __launch_bounds__(256, 2)
void mma_gemm(const __half* __restrict__ A,
              const __half* __restrict__ Bm,
              const float* __restrict__ bias,
              __half* __restrict__ Chf,
              float* __restrict__ Cow,
              int N, int K) {
    constexpr int MW    = BMt / 32;
    constexpr int NW    = 8 / MW;
    constexpr int WN    = 128 / NW;
    constexpr int NG    = WN / 16;
    constexpr int ROWS  = BMt + 128;
    constexpr int STAGE = ROWS * 128;
    constexpr int PERT  = ROWS * 8 / 256;

    extern __shared__ uint8_t smem[];
    const int tid  = threadIdx.x;
    const int wid  = tid >> 5;
    const int lane = tid & 31;
    const int brow = blockIdx.y * BMt;
    const int bcol = blockIdx.x * 128;
    const int kIters = K >> 6;

    const uint32_t smbase = smem_u32(smem);

    auto load_tile = [&](int k, int buf) {
        uint32_t sbuf = smbase + buf * STAGE;
        const int koff = k << 6;
        #pragma unroll
        for (int i = 0; i < PERT; i++) {
            int cid = tid + (i << 8);
            int row = cid >> 3;
            int col = cid & 7;
            const __half* g;
            if (row < BMt) g = A  + (size_t)(brow + row) * K + koff + col * 8;
            else           g = Bm + (size_t)(bcol + row - BMt) * K + koff + col * 8;
            uint32_t sw = row * 128 + (((uint32_t)(col ^ (row & 7))) << 4);
            CP_ASYNC16(sbuf + sw, g);
        }
    };

    const int wm = (wid % MW) * 32;
    const int wn = (wid / MW) * WN;

    float acc[2][2 * NG][4];
    #pragma unroll
    for (int mi = 0; mi < 2; mi++)
        #pragma unroll
        for (int nj = 0; nj < 2 * NG; nj++)
            #pragma unroll
            for (int r = 0; r < 4; r++) acc[mi][nj][r] = 0.0f;

    auto compute = [&](int buf) {
        uint32_t sA = smbase + buf * STAGE;
        uint32_t sB = sA + BMt * 128;
        #pragma unroll
        for (int ks = 0; ks < 4; ks++) {
            uint32_t a[2][4];
            const int c = ks * 2 + (lane >> 4);
            #pragma unroll
            for (int mi = 0; mi < 2; mi++) {
                int r = wm + mi * 16 + (lane & 15);
                uint32_t addr = sA + r * 128 + ((c ^ (r & 7)) << 4);
                LDMATRIX_X4(a[mi][0], a[mi][1], a[mi][2], a[mi][3], addr);
            }
            #pragma unroll
            for (int ng = 0; ng < NG; ng++) {
                int r = wn + ng * 16 + (lane & 15);
                uint32_t soff = r * 128 + ((c ^ (r & 7)) << 4);
                uint32_t b0, b1, b2, b3;
                LDMATRIX_X4(b0, b1, b2, b3, sB + soff);
                #pragma unroll
                for (int mi = 0; mi < 2; mi++) {
                    MMA_F16(acc[mi][ng * 2 + 0], a[mi], b0, b2);
                    MMA_F16(acc[mi][ng * 2 + 1], a[mi], b1, b3);
                }
            }
        }
    };

    load_tile(0, 0);
    asm volatile("cp.async.commit_group;" ::: "memory");
    if (kIters > 1) {
        load_tile(1, 1);
        asm volatile("cp.async.commit_group;" ::: "memory");
    }
    for (int t = 0; t < kIters; t++) {
        if (t + 1 < kIters)
            asm volatile("cp.async.wait_group 1;" ::: "memory");
        else
            asm volatile("cp.async.wait_group 0;" ::: "memory");
        __syncthreads();
        if (t + 2 < kIters) {
            load_tile(t + 2, (t + 2) % 3);
            asm volatile("cp.async.commit_group;" ::: "memory");
        }
        compute(t % 3);
    }

    const int tr = lane >> 2;
    const int tc = (lane & 3) * 2;
    #pragma unroll
    for (int mi = 0; mi < 2; mi++) {
        #pragma unroll
        for (int nj = 0; nj < 2 * NG; nj++) {
            const int col = bcol + wn + nj * 8 + tc;
            const float bb0 = bias[col], bb1 = bias[col + 1];
            #pragma unroll
            for (int rr = 0; rr < 2; rr++) {
                const int row = brow + wm + mi * 16 + rr * 8 + tr;
                float v0 = acc[mi][nj][rr * 2 + 0] + bb0;
                float v1 = acc[mi][nj][rr * 2 + 1] + bb1;
                if (RELU) { v0 = fmaxf(v0, 0.f); v1 = fmaxf(v1, 0.f); }
                if (OMODE == 1) {
                    *(__half2*)(Chf + (size_t)row * N + col) =
                        __halves2half2(__float2half_rn(v0), __float2half_rn(v1));
                } else {
                    if (col < 256) {
                        *(__half2*)(Chf + (size_t)row * C_ + col) =
                            __halves2half2(__float2half_rn(v0), __float2half_rn(v1));
                    } else {
                        float2 o; o.x = v0; o.y = v1;
                        *(float2*)(Cow + (size_t)row * NOW + (col - 256)) = o;
                    }
                }
            }
        }
    }
}

// ---------------------------------------------------------------------------
// Fused GEMM + residual + LayerNorm.
// out = LN(resid + A@B^T + bias) * s + bb  [+ pos if POSADD]
// BM=32, BN=256 (full row). 8 warps ALL in N: warp tile 32Mx32N -> 2:1
// MMA:ldmatrix ratio. 2-stage pipeline (72KB -> 2 CTA/SM preserved).
// Grid = M/32 = 1360 blocks (4.59 waves).
// FINAL: write fp32 only (network output); else fp32 + fp16.
// ---------------------------------------------------------------------------
template<int POSADD, int FINAL>
__global__ __launch_bounds__(256, 2)
void mma_gemm_ln(const __half* __restrict__ A,
                 const __half* __restrict__ Bm,
                 const float* __restrict__ bias,
                 const float* __restrict__ resid,
                 const float* __restrict__ s,
                 const float* __restrict__ bb,
                 const float* __restrict__ pos,
                 float* __restrict__ outF,
                 __half* __restrict__ outH,
                 int K) {
    constexpr int STAGE = 288 * 128;   // (32 A-rows + 256 B-rows) * 128B
    extern __shared__ uint8_t smem[];
    const int tid  = threadIdx.x;
    const int wid  = tid >> 5;
    const int lane = tid & 31;
    const int brow = blockIdx.x * 32;
    const int kIters = K >> 6;
    const uint32_t smbase = smem_u32(smem);

    auto load_tile = [&](int k, int buf) {
        uint32_t sbuf = smbase + buf * STAGE;
        const int koff = k << 6;
        #pragma unroll
        for (int i = 0; i < 9; i++) {          // 288*8/256 = 9 chunks/thread
            int cid = tid + (i << 8);
            int row = cid >> 3;
            int col = cid & 7;
            const __half* g = (row < 32)
                ? A  + (size_t)(brow + row) * K + koff + col * 8
                : Bm + (size_t)(row - 32) * K + koff + col * 8;
            uint32_t sw = row * 128 + (((uint32_t)(col ^ (row & 7))) << 4);
            CP_ASYNC16(sbuf + sw, g);
        }
    };

    const int wn = wid * 32;             // each warp: all 32 M-rows, 32 N-cols

    float acc[2][4][4];                  // [mi][nj][r], 32 regs
    #pragma unroll
    for (int mi = 0; mi < 2; mi++)
        #pragma unroll
        for (int nj = 0; nj < 4; nj++)
            #pragma unroll
            for (int r = 0; r < 4; r++) acc[mi][nj][r] = 0.0f;

    auto compute = [&](int buf) {
        uint32_t sA = smbase + buf * STAGE;
        uint32_t sB = sA + 32 * 128;
        #pragma unroll
        for (int ks = 0; ks < 4; ks++) {
            const int c = ks * 2 + (lane >> 4);
            uint32_t a[2][4];
            #pragma unroll
            for (int mi = 0; mi < 2; mi++) {
                int r = mi * 16 + (lane & 15);
                uint32_t addr = sA + r * 128 + ((c ^ (r & 7)) << 4);
                LDMATRIX_X4(a[mi][0], a[mi][1], a[mi][2], a[mi][3], addr);
            }
            #pragma unroll
            for (int ng = 0; ng < 2; ng++) {
                int r2 = wn + ng * 16 + (lane & 15);
                uint32_t soff = r2 * 128 + ((c ^ (r2 & 7)) << 4);
                uint32_t b0, b1, b2, b3;
                LDMATRIX_X4(b0, b1, b2, b3, sB + soff);
                #pragma unroll
                for (int mi = 0; mi < 2; mi++) {
                    MMA_F16(acc[mi][ng * 2 + 0], a[mi], b0, b2);
                    MMA_F16(acc[mi][ng * 2 + 1], a[mi], b1, b3);
                }
            }
        }
    };

    // 2-stage pipeline (72KB total -> 2 CTA/SM)
    load_tile(0, 0);
    asm volatile("cp.async.commit_group;" ::: "memory");
    for (int t = 0; t < kIters; t++) {
        if (t + 1 < kIters) {
            load_tile(t + 1, (t + 1) & 1);
            asm volatile("cp.async.commit_group;" ::: "memory");
            asm volatile("cp.async.wait_group 1;" ::: "memory");
        } else {
            asm volatile("cp.async.wait_group 0;" ::: "memory");
        }
        __syncthreads();
        compute(t & 1);
        __syncthreads();
    }

    // ---- Fused epilogue: residual add + two-pass LayerNorm ----
    const int tr = lane >> 2;            // 0..7
    const int tc = (lane & 3) * 2;       // 0,2,4,6
    float* red = (float*)smem;           // 32 rows x 8 warps = 1KB

    float mean_[2][2], inv_[2][2];

    // Pass A: t = acc + bias + resid; row sums
    #pragma unroll
    for (int mi = 0; mi < 2; mi++)
        #pragma unroll
        for (int rr = 0; rr < 2; rr++) {
            int rowl = mi * 16 + rr * 8 + tr;
            size_t rowg = (size_t)(brow + rowl) * C_;
            float sum = 0.f;
            #pragma unroll
            for (int nj = 0; nj < 4; nj++) {
                int col = wn + nj * 8 + tc;
                float2 rv = *(const float2*)(resid + rowg + col);
                float t0 = acc[mi][nj][rr * 2 + 0] + bias[col]     + rv.x;
                float t1 = acc[mi][nj][rr * 2 + 1] + bias[col + 1] + rv.y;
                acc[mi][nj][rr * 2 + 0] = t0;
                acc[mi][nj][rr * 2 + 1] = t1;
                sum += t0 + t1;
            }
            sum += __shfl_xor_sync(0xFFFFFFFF, sum, 1);
            sum += __shfl_xor_sync(0xFFFFFFFF, sum, 2);
            if ((lane & 3) == 0) red[rowl * 8 + wid] = sum;
        }
    __syncthreads();
    #pragma unroll
    for (int mi = 0; mi < 2; mi++)
        #pragma unroll
        for (int rr = 0; rr < 2; rr++) {
            int rowl = mi * 16 + rr * 8 + tr;
            float m = 0.f;
            #pragma unroll
            for (int wj = 0; wj < 8; wj++) m += red[rowl * 8 + wj];
            mean_[mi][rr] = m * (1.0f / C_);
        }
    __syncthreads();

    // Pass B: variance
    #pragma unroll
    for (int mi = 0; mi < 2; mi++)
        #pragma unroll
        for (int rr = 0; rr < 2; rr++) {
            int rowl = mi * 16 + rr * 8 + tr;
            float sq = 0.f;
            #pragma unroll
            for (int nj = 0; nj < 4; nj++) {
                float d0 = acc[mi][nj][rr * 2 + 0] - mean_[mi][rr];
                float d1 = acc[mi][nj][rr * 2 + 1] - mean_[mi][rr];
                sq = fmaf(d0, d0, sq);
                sq = fmaf(d1, d1, sq);
            }
            sq += __shfl_xor_sync(0xFFFFFFFF, sq, 1);
            sq += __shfl_xor_sync(0xFFFFFFFF, sq, 2);
            if ((lane & 3) == 0) red[rowl * 8 + wid] = sq;
        }
    __syncthreads();
    #pragma unroll
    for (int mi = 0; mi < 2; mi++)
        #pragma unroll
        for (int rr = 0; rr < 2; rr++) {
            int rowl = mi * 16 + rr * 8 + tr;
            float sq = 0.f;
            #pragma unroll
            for (int wj = 0; wj < 8; wj++) sq += red[rowl * 8 + wj];
            inv_[mi][rr] = rsqrtf(sq * (1.0f / C_) + 1e-5f);
        }

    // Apply + write
    #pragma unroll
    for (int mi = 0; mi < 2; mi++)
        #pragma unroll
        for (int rr = 0; rr < 2; rr++) {
            int rowl = mi * 16 + rr * 8 + tr;
            size_t rowg = (size_t)(brow + rowl) * C_;
            #pragma unroll
            for (int nj = 0; nj < 4; nj++) {
                int col = wn + nj * 8 + tc;
                float v0 = (acc[mi][nj][rr * 2 + 0] - mean_[mi][rr]) * inv_[mi][rr]
                           * s[col] + bb[col];
                float v1 = (acc[mi][nj][rr * 2 + 1] - mean_[mi][rr]) * inv_[mi][rr]
                           * s[col + 1] + bb[col + 1];
                if (POSADD) {
                    float2 pv = *(const float2*)(pos + rowg + col);
                    v0 += pv.x; v1 += pv.y;
                }
                float2 o; o.x = v0; o.y = v1;
                *(float2*)(outF + rowg + col) = o;
                if (!FINAL)
                    *(__half2*)(outH + rowg + col) =
                        __halves2half2(__float2half_rn(v0), __float2half_rn(v1));
            }
        }
}

// ---------------------------------------------------------------------------
// Deformable attention sampling, half2 channel pairs.
// ---------------------------------------------------------------------------
__constant__ int c_SW[4] = {128, 64, 32, 16};
__constant__ int c_START[4] = {0, 16384, 20480, 21504};

__global__ __launch_bounds__(256)
void deform_kernel(const __half* __restrict__ vh, const float* __restrict__ ow,
                   const float* __restrict__ ref, __half* __restrict__ oh) {
    const int tid  = threadIdx.x;
    const int wblk = tid >> 5;
    const int lane = tid & 31;
    const int sub  = lane >> 4;
    const int li   = lane & 15;
    const int bq   = blockIdx.x * 2 + (wblk >> 2);
    const int h    = ((wblk & 3) << 1) + sub;
    const int b    = bq / LQ_;

    const float* ar = ow + (size_t)bq * NOW + 256 + h * 16;
    float w[16];
    float mx = -1e30f;
    #pragma unroll
    for (int j = 0; j < 16; j++) { w[j] = ar[j]; mx = fmaxf(mx, w[j]); }
    float s = 0.0f;
    #pragma unroll
    for (int j = 0; j < 16; j++) { w[j] = expf(w[j] - mx); s += w[j]; }
    const float inv_s = 1.0f / s;

    const float refx = ref[bq * 2 + 0];
    const float refy = ref[bq * 2 + 1];
    const float* ob = ow + (size_t)bq * NOW + h * 32;
    const __half2* vb2 = (const __half2*)vh
                       + ((size_t)b * LQ_ * C_ + h * DK_) / 2 + li;

    float accx = 0.0f, accy = 0.0f;
    #pragma unroll
    for (int l = 0; l < 4; l++) {
        const int   Wl = c_SW[l];
        const float fw = (float)Wl;
        const int   st = c_START[l];
        #pragma unroll
        for (int k = 0; k < KPT; k++) {
            float ox = ob[l * 8 + k * 2 + 0];
            float oy = ob[l * 8 + k * 2 + 1];
            float x = (refx + ox * (1.0f / fw)) * (fw - 1.0f);
            float y = (refy + oy * (1.0f / fw)) * (fw - 1.0f);
            x = fminf(fmaxf(x, 0.0f), fw - 1.0f);
            y = fminf(fmaxf(y, 0.0f), fw - 1.0f);
            float x0f = floorf(x), y0f = floorf(y);
            int x0 = (int)x0f, y0 = (int)y0f;
            int x1 = min(x0 + 1, Wl - 1);
            int y1 = min(y0 + 1, Wl - 1);
            float wx = x - x0f, wy = y - y0f;
            float aw = w[l * 4 + k] * inv_s;

            float2 v00 = __half22float2(vb2[(size_t)(st + y0 * Wl + x0) * (C_ / 2)]);
            float2 v01 = __half22float2(vb2[(size_t)(st + y0 * Wl + x1) * (C_ / 2)]);
            float2 v10 = __half22float2(vb2[(size_t)(st + y1 * Wl + x0) * (C_ / 2)]);
            float2 v11 = __half22float2(vb2[(size_t)(st + y1 * Wl + x1) * (C_ / 2)]);
            float w00 = (1.0f - wx) * (1.0f - wy);
            float w01 = wx * (1.0f - wy);
            float w10 = (1.0f - wx) * wy;
            float w11 = wx * wy;
            float bx = w00 * v00.x + w01 * v01.x + w10 * v10.x + w11 * v11.x;
            float by = w00 * v00.y + w01 * v01.y + w10 * v10.y + w11 * v11.y;
            accx = fmaf(aw, bx, accx);
            accy = fmaf(aw, by, accy);
        }
    }
    ((__half2*)oh)[((size_t)bq * C_ + h * DK_) / 2 + li] =
        __halves2half2(__float2half_rn(accx), __float2half_rn(accy));
}

// ---------------------------------------------------------------------------
// Host orchestration
// ---------------------------------------------------------------------------
extern "C" void kernel_launch(void* const* d_in, const int* in_sizes, int n_in,
                              void* d_out, int out_size) {
    const float* src  = (const float*)d_in[0];
    const float* pos  = (const float*)d_in[1];
    const float* ref  = (const float*)d_in[2];
    const float* Woff = (const float*)d_in[3];
    const float* boff = (const float*)d_in[4];
    const float* Wat  = (const float*)d_in[5];
    const float* bat  = (const float*)d_in[6];
    const float* Wv   = (const float*)d_in[7];
    const float* bv   = (const float*)d_in[8];
    const float* Wo   = (const float*)d_in[9];
    const float* bo   = (const float*)d_in[10];
    const float* W1   = (const float*)d_in[11];
    const float* b1   = (const float*)d_in[12];
    const float* W2   = (const float*)d_in[13];
    const float* b2   = (const float*)d_in[14];
    const float* n1s  = (const float*)d_in[15];
    const float* n1b  = (const float*)d_in[16];
    const float* n2s  = (const float*)d_in[17];
    const float* n2b  = (const float*)d_in[18];
    float* outp = (float*)d_out;

    float *px, *pxp, *pow, *pbp;
    __half *pvh, *pah, *phh;
    __half *wproj, *wo, *w1, *w2;
    cudaGetSymbolAddress((void**)&px,     g_x);
    cudaGetSymbolAddress((void**)&pxp,    g_xp);
    cudaGetSymbolAddress((void**)&pow,    g_ow);
    cudaGetSymbolAddress((void**)&pbp,    g_bpack);
    cudaGetSymbolAddress((void**)&pvh,    g_v_h);
    cudaGetSymbolAddress((void**)&pah,    g_a_h);
    cudaGetSymbolAddress((void**)&phh,    g_h_h);
    cudaGetSymbolAddress((void**)&wproj,  g_wproj);
    cudaGetSymbolAddress((void**)&wo,     g_wo);
    cudaGetSymbolAddress((void**)&w1,     g_w1);
    cudaGetSymbolAddress((void**)&w2,     g_w2);

    const int M = MROWS;
    const int n4 = M * C_ / 4;
    const int SMEM128 = 3 * 256 * 128;   // 98304 (proj, 3-stage)
    const int SMEM64  = 3 * 192 * 128;   // 73728 (W1, 3-stage)
    const int SMEMLN  = 2 * 288 * 128;   // 73728 (fused LN, 2-stage)

    cudaFuncSetAttribute(mma_gemm<128, 0, 2>,
                         cudaFuncAttributeMaxDynamicSharedMemorySize, SMEM128);
    cudaFuncSetAttribute(mma_gemm<64, 1, 1>,
                         cudaFuncAttributeMaxDynamicSharedMemorySize, SMEM64);
    cudaFuncSetAttribute(mma_gemm_ln<0, 0>,
                         cudaFuncAttributeMaxDynamicSharedMemorySize, SMEMLN);
    cudaFuncSetAttribute(mma_gemm_ln<1, 0>,
                         cudaFuncAttributeMaxDynamicSharedMemorySize, SMEMLN);
    cudaFuncSetAttribute(mma_gemm_ln<0, 1>,
                         cudaFuncAttributeMaxDynamicSharedMemorySize, SMEMLN);

    // Weight packing (deterministic, per call)
    {
        int t0 = NL_ * NPACK * C_;
        pack_proj_w<<<(t0 + 255) / 256, 256>>>(Wv, Woff, Wat, wproj);
        int t1 = NL_ * C_ * C_;
        pack_w<<<(t1 + 255) / 256, 256>>>(Wo, wo, C_, C_);
        int t2 = NL_ * FF_ * C_;
        pack_w<<<(t2 + 255) / 256, 256>>>(W1, w1, C_, FF_);
        pack_w<<<(t2 + 255) / 256, 256>>>(W2, w2, FF_, C_);
        int tb = NL_ * NPACK;
        packb_kernel<<<(tb + 255) / 256, 256>>>(bv, boff, bat, pbp);
    }

    dim3 gAdd((n4 + 255) / 256);
    dim3 gProj(NPACK / 128, M / 128);   // (5, 340)  BM=128
    dim3 gN1024(FF_ / 128, M / 64);     // (8, 680)  BM=64
    dim3 gLNG(M / 32);                  // 1360 blocks, fused GEMM+LN
    dim3 gDef(M / 2);

    // Layer 0 addpos; later layers get it fused into LN2
    addpos_kernel<<<gAdd, 256>>>(src, pos, pxp, pah, n4);

    for (int i = 0; i < NL_; i++) {
        const float* bp_i = pbp + (size_t)i * NPACK;
        const float* bo_i = bo + (size_t)i * C_;
        const float* b1_i = b1 + (size_t)i * FF_;
        const float* b2_i = b2 + (size_t)i * C_;

        // Fused projections -> v fp16 | off/att fp32   (N=640, K=256)
        mma_gemm<128, 0, 2><<<gProj, 256, SMEM128>>>(pah,
            wproj + (size_t)i * NPACK * C_,
            bp_i, pvh, pow, NPACK, C_);

        deform_kernel<<<gDef, 256>>>(pvh, pow, ref, pah);

        // Wo GEMM + LN1 fused: x = LN(xp + attn@Wo + bo); emit px fp32 + pah fp16
        mma_gemm_ln<0, 0><<<gLNG, 256, SMEMLN>>>(pah,
            wo + (size_t)i * C_ * C_, bo_i, pxp,
            n1s + (size_t)i * C_, n1b + (size_t)i * C_, nullptr,
            px, pah, C_);

        // W1 + ReLU -> hid fp16   (N=1024, K=256)
        mma_gemm<64, 1, 1><<<gN1024, 256, SMEM64>>>(pah,
            w1 + (size_t)i * FF_ * C_,
            b1_i, phh, nullptr, FF_, C_);

        // W2 GEMM + LN2 fused
        if (i == NL_ - 1) {
            mma_gemm_ln<0, 1><<<gLNG, 256, SMEMLN>>>(phh,
                w2 + (size_t)i * C_ * FF_, b2_i, px,
                n2s + (size_t)i * C_, n2b + (size_t)i * C_, nullptr,
                outp, nullptr, FF_);
        } else {
            mma_gemm_ln<1, 0><<<gLNG, 256, SMEMLN>>>(phh,
                w2 + (size_t)i * C_ * FF_, b2_i, px,
                n2s + (size_t)i * C_, n2b + (size_t)i * C_, pos,
                pxp, pah, FF_);
        }
    }
}